// round 1
// baseline (speedup 1.0000x reference)
#include <cuda_runtime.h>
#include <cuda_bf16.h>
#include <math.h>

// ---------------- problem constants ----------------
#define V_   16384
#define D_   768
#define H_   12
#define DH_  64
#define L_   2
#define F_   3072
#define CC_  64      // chunk size
#define NB_  64
#define B_   2
#define S_   2048
#define NC_  (S_ / CC_)   // 32
#define CE_  (2 * CC_)    // 128 extended keys (prev chunk + current)
#define BS_  (B_ * S_)    // 4096 rows

// ---------------- scratch (device globals; no allocation allowed) ----------------
__device__ float g_x   [BS_ * D_];
__device__ float g_xn  [BS_ * D_];
__device__ float g_qk  [BS_ * D_];
__device__ float g_v   [BS_ * D_];
__device__ float g_att [BS_ * D_];
__device__ float g_h1  [BS_ * F_];
__device__ int   g_key [B_ * H_ * S_];
__device__ int   g_ord [B_ * H_ * S_];

// ---------------- embedding ----------------
__global__ void embed_kernel(const int* __restrict__ ids,
                             const float* __restrict__ emb,
                             const float* __restrict__ pos,
                             float* __restrict__ x) {
    int i = blockIdx.x * blockDim.x + threadIdx.x;
    if (i >= BS_ * D_) return;
    int d = i % D_;
    int row = i / D_;
    int s = row % S_;
    x[i] = emb[(size_t)ids[row] * D_ + d] + pos[(size_t)s * D_ + d];
}

// ---------------- layernorm (one block per row of 768) ----------------
__global__ void ln_kernel(const float* __restrict__ x, float* __restrict__ y,
                          const float* __restrict__ g, const float* __restrict__ b) {
    int row = blockIdx.x;
    const float* xr = x + (size_t)row * D_;
    float*       yr = y + (size_t)row * D_;
    int t = threadIdx.x;
    float v0 = xr[t], v1 = xr[t + 256], v2 = xr[t + 512];

    __shared__ float red[256];
    red[t] = v0 + v1 + v2;
    __syncthreads();
    #pragma unroll
    for (int o = 128; o > 0; o >>= 1) {
        if (t < o) red[t] += red[t + o];
        __syncthreads();
    }
    float mean = red[0] * (1.0f / D_);
    __syncthreads();

    float d0 = v0 - mean, d1 = v1 - mean, d2 = v2 - mean;
    red[t] = d0 * d0 + d1 * d1 + d2 * d2;
    __syncthreads();
    #pragma unroll
    for (int o = 128; o > 0; o >>= 1) {
        if (t < o) red[t] += red[t + o];
        __syncthreads();
    }
    float inv = rsqrtf(red[0] * (1.0f / D_) + 1e-12f);

    yr[t]       = d0 * inv * g[t]       + b[t];
    yr[t + 256] = d1 * inv * g[t + 256] + b[t + 256];
    yr[t + 512] = d2 * inv * g[t + 512] + b[t + 512];
}

// ---------------- GEMM: C[M,N] (+)= act(A[M,K] @ B[K,N] + bias) ----------------
// 128x128 tile, BK=16, 256 threads, 8x8 micro-tile. All dims multiple of 128/16.
__device__ __forceinline__ float gelu_f(float x) {
    float x3 = x * x * x;
    return 0.5f * x * (1.0f + tanhf(0.7978845608028654f * (x + 0.044715f * x3)));
}

template <bool ADD, bool BIAS, bool GELU>
__global__ void __launch_bounds__(256)
sgemm_kernel(const float* __restrict__ A, const float* __restrict__ B,
             const float* __restrict__ bias, float* __restrict__ C,
             int M, int N, int K) {
    __shared__ float As[16][132];
    __shared__ float Bs[16][128];

    const int t  = threadIdx.x;
    const int tx = t & 15;       // 0..15  -> col group
    const int ty = t >> 4;       // 0..15  -> row group
    const int m0 = blockIdx.y * 128;
    const int n0 = blockIdx.x * 128;

    float acc[8][8];
    #pragma unroll
    for (int i = 0; i < 8; i++)
        #pragma unroll
        for (int j = 0; j < 8; j++) acc[i][j] = 0.0f;

    for (int k0 = 0; k0 < K; k0 += 16) {
        // A tile: 128 rows x 16 k, stored transposed As[k][m]
        #pragma unroll
        for (int l = 0; l < 2; l++) {
            int idx = t + l * 256;            // 0..511 float4s
            int r   = idx >> 2;               // row within tile
            int kc  = (idx & 3) * 4;
            float4 av = *(const float4*)(A + (size_t)(m0 + r) * K + k0 + kc);
            As[kc + 0][r] = av.x;
            As[kc + 1][r] = av.y;
            As[kc + 2][r] = av.z;
            As[kc + 3][r] = av.w;
        }
        // B tile: 16 k x 128 n
        #pragma unroll
        for (int l = 0; l < 2; l++) {
            int idx = t + l * 256;
            int r   = idx >> 5;
            int c   = (idx & 31) * 4;
            *(float4*)(&Bs[r][c]) = *(const float4*)(B + (size_t)(k0 + r) * N + n0 + c);
        }
        __syncthreads();

        #pragma unroll
        for (int kk = 0; kk < 16; kk++) {
            float a[8], bb[8];
            #pragma unroll
            for (int i = 0; i < 8; i++) a[i]  = As[kk][ty * 8 + i];
            #pragma unroll
            for (int j = 0; j < 8; j++) bb[j] = Bs[kk][tx * 8 + j];
            #pragma unroll
            for (int i = 0; i < 8; i++)
                #pragma unroll
                for (int j = 0; j < 8; j++)
                    acc[i][j] = fmaf(a[i], bb[j], acc[i][j]);
        }
        __syncthreads();
    }

    #pragma unroll
    for (int i = 0; i < 8; i++) {
        int row = m0 + ty * 8 + i;
        #pragma unroll
        for (int j = 0; j < 8; j++) {
            int col = n0 + tx * 8 + j;
            float v = acc[i][j];
            if (BIAS) v += bias[col];
            if (GELU) v = gelu_f(v);
            size_t o = (size_t)row * N + col;
            if (ADD) C[o] += v; else C[o] = v;
        }
    }
}

// ---------------- LSH bucket ids ----------------
// one thread per (b,h,s): rotated = q @ rot[h], bucket = argmax([r, -r])
__global__ void bucket_kernel(const float* __restrict__ qk,
                              const float* __restrict__ rot,   // [H,DH,32] (layer offset applied)
                              int* __restrict__ sortkey) {
    int idx = blockIdx.x * blockDim.x + threadIdx.x;
    if (idx >= B_ * H_ * S_) return;
    int s = idx % S_;
    int h = (idx / S_) % H_;
    int b = idx / (S_ * H_);

    const float* q = qk + ((size_t)(b * S_ + s)) * D_ + h * DH_;
    float r[32];
    #pragma unroll
    for (int j = 0; j < 32; j++) r[j] = 0.0f;
    for (int d = 0; d < DH_; d++) {
        float qd = q[d];
        const float* rp = rot + ((size_t)h * DH_ + d) * 32;
        #pragma unroll
        for (int j = 0; j < 32; j++) r[j] = fmaf(qd, rp[j], r[j]);
    }
    float best = r[0];
    int bid = 0;
    #pragma unroll
    for (int j = 1; j < 32; j++)
        if (r[j] > best) { best = r[j]; bid = j; }
    #pragma unroll
    for (int j = 0; j < 32; j++) {
        float v = -r[j];
        if (v > best) { best = v; bid = 32 + j; }
    }
    sortkey[idx] = bid * S_ + s;   // unique keys -> stable
}

// ---------------- bitonic argsort of 2048 keys per (b,h) ----------------
__global__ void __launch_bounds__(1024)
sort_kernel(const int* __restrict__ sortkey, int* __restrict__ order) {
    int row = blockIdx.x;
    __shared__ int k[2048];
    __shared__ int vv[2048];
    const int* kr = sortkey + (size_t)row * S_;
    int t = threadIdx.x;
    for (int i = t; i < 2048; i += 1024) { k[i] = kr[i]; vv[i] = i; }

    for (int size = 2; size <= 2048; size <<= 1) {
        for (int stride = size >> 1; stride > 0; stride >>= 1) {
            __syncthreads();
            int pos = 2 * t - (t & (stride - 1));
            bool asc = ((pos & size) == 0);
            int a = k[pos], b = k[pos + stride];
            bool sw = asc ? (a > b) : (a < b);
            if (sw) {
                k[pos] = b;  k[pos + stride] = a;
                int va = vv[pos]; vv[pos] = vv[pos + stride]; vv[pos + stride] = va;
            }
        }
    }
    __syncthreads();
    int* orow = order + (size_t)row * S_;
    for (int i = t; i < 2048; i += 1024) orow[i] = vv[i];
}

// ---------------- chunked LSH attention ----------------
struct AttnSmem {
    float qs[CC_][DH_];        // 16 KB
    float ks[CE_][DH_ + 1];    // 33.3 KB (padded, normalized keys)
    float vs[CE_][DH_ + 1];    // 33.3 KB
    float arow[8][CE_];        // per-warp softmax row scratch
    int kpos[CE_], kb[CE_], km[CE_];
    int qpos[CC_], qb[CC_];
};

__global__ void __launch_bounds__(256)
attn_kernel(const float* __restrict__ qk, const float* __restrict__ v,
            const int* __restrict__ sortkey, const int* __restrict__ order,
            const int* __restrict__ amask, float* __restrict__ att_out) {
    extern __shared__ char sraw[];
    AttnSmem& s = *reinterpret_cast<AttnSmem*>(sraw);

    const int n = blockIdx.x, h = blockIdx.y, b = blockIdx.z;
    const int bh = b * H_ + h;
    const int* ord  = order   + (size_t)bh * S_;
    const int* skey = sortkey + (size_t)bh * S_;
    const int t = threadIdx.x;
    const int prev = (n + NC_ - 1) % NC_;

    // gather metadata for extended keys + queries
    for (int e = t; e < CE_; e += 256) {
        int si = (e < CC_) ? prev * CC_ + e : n * CC_ + (e - CC_);
        int p = ord[si];
        s.kpos[e] = p;
        s.kb[e]   = skey[p] >> 11;       // bucket = key / 2048
        s.km[e]   = amask[b * S_ + p];
    }
    for (int r = t; r < CC_; r += 256) {
        int p = ord[n * CC_ + r];
        s.qpos[r] = p;
        s.qb[r]   = skey[p] >> 11;
    }
    __syncthreads();

    // gather k/v/q rows through 'order'
    for (int idx = t; idx < CE_ * DH_; idx += 256) {
        int e = idx >> 6, d = idx & 63;
        size_t off = ((size_t)(b * S_ + s.kpos[e])) * D_ + h * DH_ + d;
        s.ks[e][d] = qk[off];
        s.vs[e][d] = v[off];
    }
    for (int idx = t; idx < CC_ * DH_; idx += 256) {
        int r = idx >> 6, d = idx & 63;
        s.qs[r][d] = qk[((size_t)(b * S_ + s.qpos[r])) * D_ + h * DH_ + d];
    }
    __syncthreads();

    // key = sqk / (||sqk|| + 1e-6)
    if (t < CE_) {
        float ss = 0.0f;
        #pragma unroll
        for (int d = 0; d < DH_; d++) ss = fmaf(s.ks[t][d], s.ks[t][d], ss);
        float sc = 1.0f / (sqrtf(ss) + 1e-6f);
        #pragma unroll
        for (int d = 0; d < DH_; d++) s.ks[t][d] *= sc;
    }
    __syncthreads();

    const int w = t >> 5, lane = t & 31;
    for (int rr = 0; rr < 8; rr++) {
        const int r  = w * 8 + rr;
        const int pq = s.qpos[r];
        const int bq = s.qb[r];

        float dv[4];
        #pragma unroll
        for (int c = 0; c < 4; c++) {
            int col = lane + 32 * c;
            float acc = 0.0f;
            #pragma unroll
            for (int d = 0; d < DH_; d++) acc = fmaf(s.qs[r][d], s.ks[col][d], acc);
            acc *= 0.125f;                       // 1/sqrt(64)
            if (bq != s.kb[col]) acc = -1e9f;    // cross-bucket
            if (s.km[col] <= 0)  acc = -1e9f;    // attention mask
            if (pq == s.kpos[col]) acc = -1e5f;  // soft self-mask (overrides)
            dv[c] = acc;
        }
        // warp softmax over 128
        float mx = fmaxf(fmaxf(dv[0], dv[1]), fmaxf(dv[2], dv[3]));
        #pragma unroll
        for (int o = 16; o > 0; o >>= 1) mx = fmaxf(mx, __shfl_xor_sync(0xffffffffu, mx, o));
        float sum = 0.0f;
        #pragma unroll
        for (int c = 0; c < 4; c++) sum += __expf(dv[c] - mx) == 0.0f ? expf(dv[c] - mx) : expf(dv[c] - mx);
        #pragma unroll
        for (int o = 16; o > 0; o >>= 1) sum += __shfl_xor_sync(0xffffffffu, sum, o);
        float inv = 1.0f / sum;
        #pragma unroll
        for (int c = 0; c < 4; c++) s.arow[w][lane + 32 * c] = expf(dv[c] - mx) * inv;
        __syncwarp();

        // out = attn @ v_ext : lane owns dims (lane, lane+32)
        float o0 = 0.0f, o1 = 0.0f;
        #pragma unroll 4
        for (int kk = 0; kk < CE_; kk++) {
            float a = s.arow[w][kk];
            o0 = fmaf(a, s.vs[kk][lane],      o0);
            o1 = fmaf(a, s.vs[kk][lane + 32], o1);
        }
        size_t obase = ((size_t)(b * S_ + pq)) * D_ + h * DH_;
        att_out[obase + lane]      = o0;   // scatter (unsort) directly
        att_out[obase + lane + 32] = o1;
        __syncwarp();
    }
}

// ---------------- host orchestration ----------------
extern "C" void kernel_launch(void* const* d_in, const int* in_sizes, int n_in,
                              void* d_out, int out_size) {
    const int*   ids   = (const int*)  d_in[0];
    const int*   amask = (const int*)  d_in[1];
    const float* emb   = (const float*)d_in[2];
    const float* pose  = (const float*)d_in[3];
    const float* rot   = (const float*)d_in[4];
    const float* Wqk   = (const float*)d_in[5];
    const float* Wv    = (const float*)d_in[6];
    const float* Wo    = (const float*)d_in[7];
    const float* ln1g  = (const float*)d_in[8];
    const float* ln1b  = (const float*)d_in[9];
    const float* ln2g  = (const float*)d_in[10];
    const float* ln2b  = (const float*)d_in[11];
    const float* W1    = (const float*)d_in[12];
    const float* b1    = (const float*)d_in[13];
    const float* W2    = (const float*)d_in[14];
    const float* b2    = (const float*)d_in[15];
    const float* lnfg  = (const float*)d_in[16];
    const float* lnfb  = (const float*)d_in[17];
    const float* Wlm   = (const float*)d_in[18];
    const float* blm   = (const float*)d_in[19];
    float* out = (float*)d_out;

    float *x, *xn, *qk, *v, *att, *h1;
    int *key, *ord;
    cudaGetSymbolAddress((void**)&x,   g_x);
    cudaGetSymbolAddress((void**)&xn,  g_xn);
    cudaGetSymbolAddress((void**)&qk,  g_qk);
    cudaGetSymbolAddress((void**)&v,   g_v);
    cudaGetSymbolAddress((void**)&att, g_att);
    cudaGetSymbolAddress((void**)&h1,  g_h1);
    cudaGetSymbolAddress((void**)&key, g_key);
    cudaGetSymbolAddress((void**)&ord, g_ord);

    static bool attr_set = false;
    if (!attr_set) {
        cudaFuncSetAttribute(attn_kernel, cudaFuncAttributeMaxDynamicSharedMemorySize,
                             (int)sizeof(AttnSmem));
        attr_set = true;
    }

    // embeddings
    {
        int total = BS_ * D_;
        embed_kernel<<<(total + 255) / 256, 256>>>(ids, emb, pose, x);
    }

    for (int l = 0; l < L_; l++) {
        // LN1
        ln_kernel<<<BS_, 256>>>(x, xn, ln1g + l * D_, ln1b + l * D_);
        // qk / v projections
        {
            dim3 grid(D_ / 128, BS_ / 128);
            sgemm_kernel<false, false, false><<<grid, 256>>>(xn, Wqk + (size_t)l * D_ * D_, nullptr, qk, BS_, D_, D_);
            sgemm_kernel<false, false, false><<<grid, 256>>>(xn, Wv  + (size_t)l * D_ * D_, nullptr, v,  BS_, D_, D_);
        }
        // buckets + sort
        bucket_kernel<<<(B_ * H_ * S_ + 255) / 256, 256>>>(qk, rot + (size_t)l * H_ * DH_ * (NB_ / 2), key);
        sort_kernel<<<B_ * H_, 1024>>>(key, ord);
        // chunked attention (gathers through order, scatters unsorted output)
        {
            dim3 grid(NC_, H_, B_);
            attn_kernel<<<grid, 256, sizeof(AttnSmem)>>>(qk, v, key, ord, amask, att);
        }
        // x += att @ Wo
        {
            dim3 grid(D_ / 128, BS_ / 128);
            sgemm_kernel<true, false, false><<<grid, 256>>>(att, Wo + (size_t)l * D_ * D_, nullptr, x, BS_, D_, D_);
        }
        // FFN
        ln_kernel<<<BS_, 256>>>(x, xn, ln2g + l * D_, ln2b + l * D_);
        {
            dim3 grid1(F_ / 128, BS_ / 128);
            sgemm_kernel<false, true, true><<<grid1, 256>>>(xn, W1 + (size_t)l * D_ * F_, b1 + (size_t)l * F_, h1, BS_, F_, D_);
            dim3 grid2(D_ / 128, BS_ / 128);
            sgemm_kernel<true, true, false><<<grid2, 256>>>(h1, W2 + (size_t)l * F_ * D_, b2 + (size_t)l * D_, x, BS_, D_, F_);
        }
    }

    // final LN + LM head
    ln_kernel<<<BS_, 256>>>(x, xn, lnfg, lnfb);
    {
        dim3 grid(V_ / 128, BS_ / 128);
        sgemm_kernel<false, true, false><<<grid, 256>>>(xn, Wlm, blm, out, BS_, V_, D_);
    }
}